// round 7
// baseline (speedup 1.0000x reference)
#include <cuda_runtime.h>
#include <cstdint>

// Problem constants
#define Bn 16
#define Cn 256
#define Hn 128
#define Wn 128
#define HW 16384              // 2^14
#define HW4 4096
#define CHW4 1048576          // 2^20

// Persistent-kernel geometry
#define NBLK 256              // blocks (all co-resident: 2/SM x 148 SMs = 296 >= 256)
#define NTHR 512
#define PX 64                 // pixels per block tile (one batch = 256 tiles)
#define PX4 16
// SMEM: x tile 4096 float4 (64 KiB) + aux 512 float4 (8 KiB) + x1s 64 f (256 B)
#define SMEM_BYTES ((4096 + 512) * 16 + 256)

// Globals
__device__ float    g_s[Bn * HW];    // channel sums, 1 MiB
__device__ unsigned g_bar_count = 0; // grid-barrier arrivals (returns to 0 each use)
__device__ unsigned g_bar_gen   = 0; // grid-barrier generation (monotonic)

__global__ void __launch_bounds__(NTHR, 2)
fused_kernel(const float4* __restrict__ x,
             const float* __restrict__ f,
             float4* __restrict__ out) {
    extern __shared__ float4 smem4[];
    float4* xs  = smem4;               // [Cn*PX4] x tile: idx c*16+px4
    float4* aux = smem4 + Cn * PX4;    // [32*16] partial sums
    float*  x1s = (float*)(aux + 512); // [64] conv result for tile

    const int tid = threadIdx.x;
    const int t   = blockIdx.x;        // tile id 0..255
    const int px4 = tid & 15;          // float4-pixel within tile
    const int cg  = tid >> 4;          // channel group 0..31

    // filter -> regs (once)
    float fw[9];
#pragma unroll
    for (int k = 0; k < 9; ++k) fw[k] = f[k];

    for (int b = 0; b < Bn; ++b) {
        const size_t base = (size_t)b * CHW4 + (size_t)t * PX4 + px4;

        // ---- Phase 1: load x tile to SMEM + partial channel sums ----
        float4 part = make_float4(0.f, 0.f, 0.f, 0.f);
#pragma unroll
        for (int p = 0; p < 8; ++p) {
            int c = cg + p * 32;                       // covers 0..255
            float4 v = x[base + (size_t)c * HW4];
            xs[c * PX4 + px4] = v;
            part.x += v.x; part.y += v.y; part.z += v.z; part.w += v.w;
        }
        aux[cg * PX4 + px4] = part;
        __syncthreads();

        if (tid < PX4) {
            float4 acc = make_float4(0.f, 0.f, 0.f, 0.f);
#pragma unroll
            for (int gg = 0; gg < 32; ++gg) {
                float4 v = aux[gg * PX4 + tid];
                acc.x += v.x; acc.y += v.y; acc.z += v.z; acc.w += v.w;
            }
            ((float4*)g_s)[(size_t)b * HW4 + t * PX4 + tid] = acc;
        }
        __syncthreads();

        // ---- Grid barrier (all blocks' s writes visible before conv) ----
        if (tid == 0) {
            __threadfence();
            unsigned gen = atomicAdd(&g_bar_gen, 0u);
            if (atomicAdd(&g_bar_count, 1u) == NBLK - 1) {
                g_bar_count = 0;
                __threadfence();
                atomicAdd(&g_bar_gen, 1u);
            } else {
                while (atomicAdd(&g_bar_gen, 0u) == gen) { }
            }
            __threadfence();
        }
        __syncthreads();

        // ---- Phase 2: conv3x3 (cross-correlation, zero pad) on own tile ----
        if (tid < PX) {
            int p = t * PX + tid;      // pixel within batch
            int h = p >> 7;
            int w = p & (Wn - 1);
            const float* sb = g_s + b * HW;
            float acc = 0.f;
#pragma unroll
            for (int di = 0; di < 3; ++di) {
                int hh = h + di - 1;
                if (hh < 0 || hh >= Hn) continue;
#pragma unroll
                for (int dj = 0; dj < 3; ++dj) {
                    int ww = w + dj - 1;
                    if (ww < 0 || ww >= Wn) continue;
                    acc += sb[hh * Wn + ww] * fw[di * 3 + dj];
                }
            }
            x1s[tid] = acc;
        }
        __syncthreads();

        // ---- Phase 3: out = x(SMEM) - x1, store ----
        float4 bv = ((const float4*)x1s)[px4];
#pragma unroll
        for (int p = 0; p < 8; ++p) {
            int c = cg + p * 32;
            float4 v = xs[c * PX4 + px4];
            float4 o;
            o.x = v.x - bv.x; o.y = v.y - bv.y;
            o.z = v.z - bv.z; o.w = v.w - bv.w;
            out[base + (size_t)c * HW4] = o;
        }
        __syncthreads();   // xs reused next iteration
    }
}

// ---------------------------------------------------------------------------
extern "C" void kernel_launch(void* const* d_in, const int* in_sizes, int n_in,
                              void* d_out, int out_size) {
    const float* x = (const float*)d_in[0];   // (16,256,128,128) fp32
    const float* f = (const float*)d_in[1];   // (3,3) fp32
    float* out = (float*)d_out;

    static bool init = false;
    if (!init) {
        cudaFuncSetAttribute(fused_kernel,
                             cudaFuncAttributeMaxDynamicSharedMemorySize,
                             SMEM_BYTES);
        init = true;
    }

    fused_kernel<<<NBLK, NTHR, SMEM_BYTES>>>(
        (const float4*)x, f, (float4*)out);
}

// round 8
// speedup vs baseline: 1.1292x; 1.1292x over previous
#include <cuda_runtime.h>
#include <cstdint>

// Problem constants
#define Bn 16
#define Cn 256
#define Hn 128
#define Wn 128
#define HW 16384              // 2^14
#define HW4 4096
#define CHW4 1048576          // 2^20

// Geometry: 256 blocks, each owns one 64-pixel (half-row) tile per batch.
#define NBLK 256
#define NTHR 512
#define PX 64
#define PX4 16
#define SMEM_BYTES ((4096 + 512) * 16 + 256)

// Globals
__device__ float    g_s[Bn * HW];        // channel sums (all batches), 1 MiB
__device__ unsigned g_flag[Bn * NBLK];   // per-(batch,tile) "s ready" flags

// ---------------------------------------------------------------------------
__global__ void reset_flags_kernel() {
    g_flag[blockIdx.x * blockDim.x + threadIdx.x] = 0u;
}

// ---------------------------------------------------------------------------
__global__ void __launch_bounds__(NTHR, 2)
fused_kernel(const float4* __restrict__ x,
             const float* __restrict__ f,
             float4* __restrict__ out) {
    extern __shared__ float4 smem4[];
    float4* xs  = smem4;               // [Cn*PX4] x tile
    float4* aux = smem4 + Cn * PX4;    // [32*16] partial sums
    float*  x1s = (float*)(aux + 512); // [64] conv result

    const int tid = threadIdx.x;
    const int t   = blockIdx.x;        // tile id 0..255 (row = t>>1, half = t&1)
    const int px4 = tid & 15;
    const int cg  = tid >> 4;          // 0..31

    float fw[9];
#pragma unroll
    for (int k = 0; k < 9; ++k) fw[k] = f[k];

    for (int b = 0; b < Bn; ++b) {
        const size_t base = (size_t)b * CHW4 + (size_t)t * PX4 + px4;

        // ---- Phase 1: load x tile to SMEM + partial channel sums ----
        float4 part = make_float4(0.f, 0.f, 0.f, 0.f);
#pragma unroll
        for (int p = 0; p < 8; ++p) {
            int c = cg + p * 32;
            float4 v = x[base + (size_t)c * HW4];
            xs[c * PX4 + px4] = v;
            part.x += v.x; part.y += v.y; part.z += v.z; part.w += v.w;
        }
        aux[cg * PX4 + px4] = part;
        __syncthreads();

        if (tid < PX4) {
            float4 acc = make_float4(0.f, 0.f, 0.f, 0.f);
#pragma unroll
            for (int gg = 0; gg < 32; ++gg) {
                float4 v = aux[gg * PX4 + tid];
                acc.x += v.x; acc.y += v.y; acc.z += v.z; acc.w += v.w;
            }
            ((float4*)g_s)[(size_t)b * HW4 + t * PX4 + tid] = acc;
            __threadfence();                      // release own s writes
        }
        __syncthreads();
        if (tid == 0) atomicExch(&g_flag[b * NBLK + t], 1u);

        // ---- Acquire neighbor s tiles (rows r-1..r+1, both halves) ----
        {
            int r = t >> 1;
            if (tid < 6) {
                int rr = r - 1 + (tid >> 1);
                int nt = (rr << 1) + (tid & 1);
                if (rr >= 0 && rr < Hn && nt != t) {
                    unsigned* fl = &g_flag[b * NBLK + nt];
                    while (atomicAdd(fl, 0u) == 0u) __nanosleep(64);
                }
                __threadfence();                  // acquire
            }
        }
        __syncthreads();

        // ---- Phase 2: conv3x3 (cross-corr, zero pad) on own tile ----
        if (tid < PX) {
            int p = t * PX + tid;
            int h = p >> 7;
            int w = p & (Wn - 1);
            const float* sb = g_s + b * HW;
            float acc = 0.f;
#pragma unroll
            for (int di = 0; di < 3; ++di) {
                int hh = h + di - 1;
                if (hh < 0 || hh >= Hn) continue;
#pragma unroll
                for (int dj = 0; dj < 3; ++dj) {
                    int ww = w + dj - 1;
                    if (ww < 0 || ww >= Wn) continue;
                    acc += sb[hh * Wn + ww] * fw[di * 3 + dj];
                }
            }
            x1s[tid] = acc;
        }
        __syncthreads();

        // ---- Phase 3: out = x(SMEM) - x1 ----
        float4 bv = ((const float4*)x1s)[px4];
#pragma unroll
        for (int p = 0; p < 8; ++p) {
            int c = cg + p * 32;
            float4 v = xs[c * PX4 + px4];
            float4 o;
            o.x = v.x - bv.x; o.y = v.y - bv.y;
            o.z = v.z - bv.z; o.w = v.w - bv.w;
            out[base + (size_t)c * HW4] = o;
        }
        __syncthreads();   // xs reused next iteration
    }
}

// ---------------------------------------------------------------------------
extern "C" void kernel_launch(void* const* d_in, const int* in_sizes, int n_in,
                              void* d_out, int out_size) {
    const float* x = (const float*)d_in[0];   // (16,256,128,128) fp32
    const float* f = (const float*)d_in[1];   // (3,3) fp32
    float* out = (float*)d_out;

    static bool init = false;
    if (!init) {
        cudaFuncSetAttribute(fused_kernel,
                             cudaFuncAttributeMaxDynamicSharedMemorySize,
                             SMEM_BYTES);
        init = true;
    }

    reset_flags_kernel<<<(Bn * NBLK) / 256, 256>>>();
    fused_kernel<<<NBLK, NTHR, SMEM_BYTES>>>(
        (const float4*)x, f, (float4*)out);
}

// round 10
// speedup vs baseline: 1.2007x; 1.0633x over previous
#include <cuda_runtime.h>
#include <cstdint>

// Problem constants
#define Bn 16
#define Cn 256
#define Hn 128
#define Wn 128
#define HW 16384              // 2^14
#define HW4 4096
#define CHW4 1048576          // 2^20
#define BHW (Bn*HW)           // 262144
#define BHW4 (BHW/4)          // 65536
#define TOTAL4 (Bn*CHW4)      // 16777216

// Scratch
__device__ float g_s[BHW];    // channel sums, 1 MiB
__device__ float g_x1[BHW];   // conv result, 1 MiB

// ---------------------------------------------------------------------------
// K1: s[b,hw] = sum_c x[b,c,hw], block-level reduction, no partials in DRAM.
// 4096 blocks x 256 threads (256 blocks per batch; each block covers 16
// float4-pixels x all 256 channels). Thread (cg,px4): cg=tid>>4 sums channels
// cg*16..cg*16+15 for its float4-pixel; SMEM combine collapses 16 cgroups.
// MLP = 16 outstanding LDG.128 per thread.
// ---------------------------------------------------------------------------
__global__ void __launch_bounds__(256) reduce_s_kernel(const float4* __restrict__ x,
                                                       float4* __restrict__ s4) {
    __shared__ float4 aux[256];          // [cg][px4]

    const int tid = threadIdx.x;
    const int px4 = tid & 15;            // 0..15
    const int cg  = tid >> 4;            // 0..15
    const int blk = blockIdx.x;          // 0..4095
    const int b   = blk >> 8;            // 256 blocks per batch
    const int p0  = (blk & 255) * 16 + px4;  // float4-pixel within batch 0..4095

    const float4* p = x + (size_t)b * CHW4 + (size_t)cg * 16 * HW4 + p0;

    float4 acc = make_float4(0.f, 0.f, 0.f, 0.f);
#pragma unroll
    for (int c = 0; c < 16; ++c) {
        float4 v = p[(size_t)c * HW4];
        acc.x += v.x; acc.y += v.y; acc.z += v.z; acc.w += v.w;
    }
    aux[tid] = acc;
    __syncthreads();

    // combine 16 cgroups; threads 0..15 each own one px4
    if (tid < 16) {
        float4 a = aux[tid];
#pragma unroll
        for (int g = 1; g < 16; ++g) {
            float4 v = aux[g * 16 + tid];
            a.x += v.x; a.y += v.y; a.z += v.z; a.w += v.w;
        }
        s4[(size_t)b * HW4 + (blk & 255) * 16 + tid] = a;
    }
}

// ---------------------------------------------------------------------------
// K2: x1 = conv3x3(s), zero pad, cross-correlation. 262144 threads, L2-resident.
// ---------------------------------------------------------------------------
__global__ void __launch_bounds__(256) conv3_kernel(const float* __restrict__ s,
                                                    const float* __restrict__ f,
                                                    float* __restrict__ x1) {
    int i = blockIdx.x * blockDim.x + threadIdx.x;  // 0 .. BHW-1
    int b  = i >> 14;
    int hw = i & (HW - 1);
    int h  = hw >> 7;
    int w  = hw & (Wn - 1);

    float fw[9];
#pragma unroll
    for (int k = 0; k < 9; ++k) fw[k] = f[k];

    const float* sb = s + b * HW;
    float acc = 0.f;
#pragma unroll
    for (int di = 0; di < 3; ++di) {
        int hh = h + di - 1;
        if (hh < 0 || hh >= Hn) continue;
#pragma unroll
        for (int dj = 0; dj < 3; ++dj) {
            int ww = w + dj - 1;
            if (ww < 0 || ww >= Wn) continue;
            acc += sb[hh * Wn + ww] * fw[di * 3 + dj];
        }
    }
    x1[i] = acc;
}

// ---------------------------------------------------------------------------
// K3: out = x - x1 (broadcast over C), ILP=2 (exact R5 best variant).
// 8388608 threads; each handles float4 elements i and i+TOTAL4/2.
// ---------------------------------------------------------------------------
__global__ void __launch_bounds__(256) sub_kernel(const float4* __restrict__ x,
                                                  const float4* __restrict__ x1,
                                                  float4* __restrict__ out) {
    int i = blockIdx.x * blockDim.x + threadIdx.x;  // 0 .. 8388607
    int i2 = i + (TOTAL4 / 2);

    float4 xa = x[i];
    float4 xb = x[i2];
    float4 ba = __ldg(&x1[((i  >> 20) << 12) + (i  & 4095)]);
    float4 bb = __ldg(&x1[((i2 >> 20) << 12) + (i2 & 4095)]);

    float4 oa, ob;
    oa.x = xa.x - ba.x; oa.y = xa.y - ba.y; oa.z = xa.z - ba.z; oa.w = xa.w - ba.w;
    ob.x = xb.x - bb.x; ob.y = xb.y - bb.y; ob.z = xb.z - bb.z; ob.w = xb.w - bb.w;
    out[i]  = oa;
    out[i2] = ob;
}

// ---------------------------------------------------------------------------
extern "C" void kernel_launch(void* const* d_in, const int* in_sizes, int n_in,
                              void* d_out, int out_size) {
    const float* x = (const float*)d_in[0];   // (16,256,128,128) fp32
    const float* f = (const float*)d_in[1];   // (3,3) fp32
    float* out = (float*)d_out;

    static float* s_ptr  = nullptr;
    static float* x1_ptr = nullptr;
    if (s_ptr == nullptr) {
        cudaGetSymbolAddress((void**)&s_ptr,  g_s);
        cudaGetSymbolAddress((void**)&x1_ptr, g_x1);
    }

    // K1: channel sums (reads 256 MiB, writes 1 MiB)
    reduce_s_kernel<<<4096, 256>>>((const float4*)x, (float4*)s_ptr);

    // K2: conv3x3 (L2-resident)
    conv3_kernel<<<BHW / 256, 256>>>(s_ptr, f, x1_ptr);

    // K3: broadcast subtract (reads 256 MiB + 1 MiB, writes 256 MiB)
    sub_kernel<<<(TOTAL4 / 2) / 256, 256>>>(
        (const float4*)x, (const float4*)x1_ptr, (float4*)out);
}